// round 2
// baseline (speedup 1.0000x reference)
#include <cuda_runtime.h>
#include <mma.h>
#include <cstdint>

#define NODES 50000
#define CE    64
#define CN    256
#define COUT  256

// scratch accumulator for segment-sum (12.8 MB) — __device__ global, no alloc
__device__ float g_A[(size_t)NODES * CE];

// ---------------------------------------------------------------------------
// Kernel 1: zero the accumulator
// ---------------------------------------------------------------------------
__global__ void zero_kernel() {
    int i = blockIdx.x * blockDim.x + threadIdx.x;
    const int n4 = NODES * CE / 4;
    if (i < n4) {
        reinterpret_cast<float4*>(g_A)[i] = make_float4(0.f, 0.f, 0.f, 0.f);
    }
}

// ---------------------------------------------------------------------------
// Kernel 2: edge scatter.  One thread per (edge, 16B chunk): 16 threads/edge.
// Fully coalesced 410 MB read of edge_attr, red.v4.f32 into g_A.
// ---------------------------------------------------------------------------
__global__ void scatter_kernel(const float4* __restrict__ ea,
                               const int* __restrict__ row_idx,
                               int total16) {
    int i = blockIdx.x * 256 + threadIdx.x;
    if (i >= total16) return;
    int e = i >> 4;          // edge id
    int t = i & 15;          // float4 chunk within the 64-channel row
    int r = __ldg(row_idx + e);
    float4 v = __ldg(ea + i);
    float* dst = g_A + (size_t)r * CE + t * 4;
    asm volatile("red.global.add.v4.f32 [%0], {%1, %2, %3, %4};"
                 :: "l"(dst), "f"(v.x), "f"(v.y), "f"(v.z), "f"(v.w)
                 : "memory");
}

// ---------------------------------------------------------------------------
// Kernel 3: fused GEMM  out = relu([A/D | X] @ [W_pass; W_self] + bias)
//   M = 50000 (nodes), N = 256, K = 320 (64 from A/D, 256 from X)
//   CTA tile: 128 x 256, K-step 32.  512 threads = 16 warps in 4(M) x 4(N).
//   Warp tile: 32 x 64 = 2x4 wmma m16n16k8 tf32 tiles.
//   Bias folded in by preloading accumulators from bias-replicated smem.
// ---------------------------------------------------------------------------
using namespace nvcuda;

__global__ __launch_bounds__(512, 1)
void gemm_kernel(const float* __restrict__ D,
                 const float* __restrict__ X,
                 const float* __restrict__ Wp,
                 const float* __restrict__ bp,
                 const float* __restrict__ Ws,
                 const float* __restrict__ bs,
                 float* __restrict__ out,
                 int nNodes) {
    __shared__ float As[128][32];   // 16 KB
    __shared__ float Bs[32][256];   // 32 KB  (total 48 KB static)

    const int tid  = threadIdx.x;
    const int warp = tid >> 5;
    const int wm   = warp >> 2;     // 0..3  (M position, 32 rows each)
    const int wn   = warp & 3;      // 0..3  (N position, 64 cols each)
    const int row0 = blockIdx.x * 128;

    // ---- bias (b_pass + b_self) replicated into Bs rows 0..15 ----
    for (int i = tid; i < 16 * 256; i += 512) {
        int c = i & 255;
        Bs[i >> 8][c] = __ldg(bp + c) + __ldg(bs + c);
    }
    __syncthreads();

    wmma::fragment<wmma::accumulator, 16, 16, 8, float> acc[2][4];
#pragma unroll
    for (int mi = 0; mi < 2; mi++)
#pragma unroll
        for (int ni = 0; ni < 4; ni++)
            wmma::load_matrix_sync(acc[mi][ni], &Bs[0][wn * 64 + ni * 16], 256,
                                   wmma::mem_row_major);
    __syncthreads();

    // ---- main K loop: 10 steps of 32 ----
    for (int ks = 0; ks < 10; ks++) {
        const int k0 = ks * 32;

        // load As tile [128 x 32]: k<64 -> A/D, else X
#pragma unroll
        for (int i = 0; i < 8; i++) {
            int idx = tid + i * 512;
            int r = idx >> 5, kk = idx & 31;
            int k = k0 + kk;
            int gr = row0 + r;
            float v = 0.f;
            if (gr < nNodes) {
                if (k < 64)
                    v = g_A[(size_t)gr * CE + k] * __frcp_rn(__ldg(D + gr));
                else
                    v = __ldg(X + (size_t)gr * CN + (k - 64));
            }
            As[r][kk] = v;
        }

        // load Bs tile [32 x 256]: k<64 -> W_pass, else W_self
#pragma unroll
        for (int i = 0; i < 16; i++) {
            int idx = tid + i * 512;
            int r = idx >> 8, c = idx & 255;
            int k = k0 + r;
            Bs[r][c] = (k < 64) ? __ldg(Wp + k * COUT + c)
                                : __ldg(Ws + (size_t)(k - 64) * COUT + c);
        }
        __syncthreads();

#pragma unroll
        for (int kk8 = 0; kk8 < 4; kk8++) {
            wmma::fragment<wmma::matrix_a, 16, 16, 8, wmma::precision::tf32,
                           wmma::row_major> af[2];
            wmma::fragment<wmma::matrix_b, 16, 16, 8, wmma::precision::tf32,
                           wmma::row_major> bf[4];
#pragma unroll
            for (int mi = 0; mi < 2; mi++) {
                wmma::load_matrix_sync(af[mi], &As[wm * 32 + mi * 16][kk8 * 8], 32);
#pragma unroll
                for (int t = 0; t < af[mi].num_elements; t++)
                    af[mi].x[t] = wmma::__float_to_tf32(af[mi].x[t]);
            }
#pragma unroll
            for (int ni = 0; ni < 4; ni++) {
                wmma::load_matrix_sync(bf[ni], &Bs[kk8 * 8][wn * 64 + ni * 16], 256);
#pragma unroll
                for (int t = 0; t < bf[ni].num_elements; t++)
                    bf[ni].x[t] = wmma::__float_to_tf32(bf[ni].x[t]);
            }
#pragma unroll
            for (int mi = 0; mi < 2; mi++)
#pragma unroll
                for (int ni = 0; ni < 4; ni++)
                    wmma::mma_sync(acc[mi][ni], af[mi], bf[ni], acc[mi][ni]);
        }
        __syncthreads();
    }

    // ---- ReLU on accumulator registers (elementwise, mapping-agnostic) ----
#pragma unroll
    for (int mi = 0; mi < 2; mi++)
#pragma unroll
        for (int ni = 0; ni < 4; ni++)
#pragma unroll
            for (int t = 0; t < acc[mi][ni].num_elements; t++)
                acc[mi][ni].x[t] = fmaxf(acc[mi][ni].x[t], 0.f);

    if (row0 + 128 <= nNodes) {
        // full tile: store fragments directly
#pragma unroll
        for (int mi = 0; mi < 2; mi++)
#pragma unroll
            for (int ni = 0; ni < 4; ni++)
                wmma::store_matrix_sync(
                    out + (size_t)(row0 + wm * 32 + mi * 16) * COUT + wn * 64 + ni * 16,
                    acc[mi][ni], COUT, wmma::mem_row_major);
    } else {
        // tail CTA: stage 32-row chunks through Bs with row guards
        for (int chunk = 0; chunk < 4; chunk++) {
            __syncthreads();
            if (wm == chunk) {
#pragma unroll
                for (int mi = 0; mi < 2; mi++)
#pragma unroll
                    for (int ni = 0; ni < 4; ni++)
                        wmma::store_matrix_sync(&Bs[mi * 16][wn * 64 + ni * 16],
                                                acc[mi][ni], 256,
                                                wmma::mem_row_major);
            }
            __syncthreads();
            int base = row0 + chunk * 32;
            for (int idx = tid; idx < 32 * 256; idx += 512) {
                int r = idx >> 8, c = idx & 255;
                int gr = base + r;
                if (gr < nNodes) out[(size_t)gr * COUT + c] = Bs[r][c];
            }
        }
    }
}

// ---------------------------------------------------------------------------
extern "C" void kernel_launch(void* const* d_in, const int* in_sizes, int n_in,
                              void* d_out, int out_size) {
    const float*  D   = (const float*)d_in[0];
    const int*    row = (const int*)d_in[1];
    const float4* ea  = (const float4*)d_in[2];
    const float*  X   = (const float*)d_in[3];
    const float*  Wp  = (const float*)d_in[4];
    const float*  bp  = (const float*)d_in[5];
    const float*  Ws  = (const float*)d_in[6];
    const float*  bs  = (const float*)d_in[7];
    float* out = (float*)d_out;

    const int nNodes = in_sizes[0];
    const int E      = in_sizes[1];

    // 1) zero accumulator
    {
        int n4 = NODES * CE / 4;
        zero_kernel<<<(n4 + 255) / 256, 256>>>();
    }
    // 2) scatter edges
    {
        int total16 = E * 16;
        scatter_kernel<<<(total16 + 255) / 256, 256>>>(ea, row, total16);
    }
    // 3) fused GEMM + bias + ReLU
    {
        int grid = (nNodes + 127) / 128;
        gemm_kernel<<<grid, 512>>>(D, X, Wp, bp, Ws, bs, out, nNodes);
    }
}

// round 3
// speedup vs baseline: 1.6674x; 1.6674x over previous
#include <cuda_runtime.h>
#include <mma.h>
#include <cstdint>

#define NODES 50000
#define CE    64
#define CN    256
#define COUT  256
#define KSTEP 16
#define NKS   20   // 320 / 16

// scratch: pre-scaled accumulator A/D (12.8 MB) + invD — __device__ globals
__device__ float g_A[(size_t)NODES * CE];
__device__ float g_invD[NODES];

// ---------------------------------------------------------------------------
// cp.async helpers
// ---------------------------------------------------------------------------
__device__ __forceinline__ void cp_async16(void* smem, const void* gsrc, bool pred) {
    uint32_t s = (uint32_t)__cvta_generic_to_shared(smem);
    int sz = pred ? 16 : 0;
    asm volatile("cp.async.cg.shared.global [%0], [%1], 16, %2;\n"
                 :: "r"(s), "l"(gsrc), "r"(sz));
}
#define CP_COMMIT() asm volatile("cp.async.commit_group;\n" ::: "memory")
#define CP_WAIT(n)  asm volatile("cp.async.wait_group %0;\n" :: "n"(n) : "memory")

// ---------------------------------------------------------------------------
// Kernel 1: zero accumulator + precompute invD
// ---------------------------------------------------------------------------
__global__ void zero_kernel(const float* __restrict__ D) {
    int i = blockIdx.x * blockDim.x + threadIdx.x;
    if (i < NODES) g_invD[i] = __frcp_rn(__ldg(D + i));
    if (i < NODES * CE / 4)
        reinterpret_cast<float4*>(g_A)[i] = make_float4(0.f, 0.f, 0.f, 0.f);
}

// ---------------------------------------------------------------------------
// Kernel 2: edge scatter, pre-scaled by invD[dest].
// 16 threads/edge, coalesced 410MB read, red.v4.f32 into g_A.
// ---------------------------------------------------------------------------
__global__ void scatter_kernel(const float4* __restrict__ ea,
                               const int* __restrict__ row_idx,
                               int total16) {
    int i = blockIdx.x * 256 + threadIdx.x;
    if (i >= total16) return;
    int e = i >> 4;
    int t = i & 15;
    int r = __ldg(row_idx + e);
    float s = __ldg(g_invD + r);
    float4 v = __ldg(ea + i);
    v.x *= s; v.y *= s; v.z *= s; v.w *= s;
    float* dst = g_A + (size_t)r * CE + t * 4;
    asm volatile("red.global.add.v4.f32 [%0], {%1, %2, %3, %4};"
                 :: "l"(dst), "f"(v.x), "f"(v.y), "f"(v.z), "f"(v.w)
                 : "memory");
}

// ---------------------------------------------------------------------------
// Kernel 3: fused GEMM  out = relu([A/D | X] @ [W_pass; W_self] + bias)
//   M=50000, N=256, K=320.  CTA 128x128, K-step 16, 2-stage cp.async.
//   256 threads = 8 warps in 4(M) x 2(N); warp tile 32x64 = 2x4 tf32 frags.
// ---------------------------------------------------------------------------
using namespace nvcuda;

__device__ __forceinline__ void load_stage(
    float (*As)[24], float (*Bs)[136], int ks, int row0, int col0, int nNodes,
    const float* __restrict__ X, const float* __restrict__ Wp,
    const float* __restrict__ Ws, int tid)
{
    const int k0 = ks * KSTEP;
    // As: 128 rows x 16 k  (512 float4, 2 per thread)
#pragma unroll
    for (int i = 0; i < 2; i++) {
        int j  = tid + i * 256;
        int r  = j >> 2, c4 = (j & 3) * 4;
        int gr = row0 + r;
        bool ok = gr < nNodes;
        int grc = ok ? gr : 0;
        const float* src = (k0 < 64)
            ? (g_A + (size_t)grc * CE + (k0 + c4))
            : (X   + (size_t)grc * CN + (k0 - 64 + c4));
        cp_async16(&As[r][c4], src, ok);
    }
    // Bs: 16 k-rows x 128 cols  (512 float4, 2 per thread)
#pragma unroll
    for (int i = 0; i < 2; i++) {
        int j = tid + i * 256;
        int r = j >> 5, c4 = (j & 31) * 4;
        int k = k0 + r;
        const float* src = (k < 64)
            ? (Wp + (size_t)k * COUT + col0 + c4)
            : (Ws + (size_t)(k - 64) * COUT + col0 + c4);
        cp_async16(&Bs[r][c4], src, true);
    }
}

__global__ __launch_bounds__(256, 2)
void gemm_kernel(const float* __restrict__ X,
                 const float* __restrict__ Wp, const float* __restrict__ bp,
                 const float* __restrict__ Ws, const float* __restrict__ bs,
                 float* __restrict__ out, int nNodes) {
    __shared__ float As[2][128][24];   // 24 KB
    __shared__ float Bs[2][16][136];   // 17 KB  (total ~41 KB static)

    const int tid  = threadIdx.x;
    const int warp = tid >> 5;
    const int wm   = warp >> 1;        // 0..3, 32 rows each
    const int wn   = warp & 1;         // 0..1, 64 cols each
    const int row0 = blockIdx.x * 128;
    const int col0 = blockIdx.y * 128;

    // bias (b_pass + b_self) replicated into Bs[0] rows 0..15
    for (int i = tid; i < 16 * 128; i += 256) {
        int r = i >> 7, c = i & 127;
        Bs[0][r][c] = __ldg(bp + col0 + c) + __ldg(bs + col0 + c);
    }
    __syncthreads();

    wmma::fragment<wmma::accumulator, 16, 16, 8, float> acc[2][4];
#pragma unroll
    for (int mi = 0; mi < 2; mi++)
#pragma unroll
        for (int ni = 0; ni < 4; ni++)
            wmma::load_matrix_sync(acc[mi][ni], &Bs[0][0][wn * 64 + ni * 16], 136,
                                   wmma::mem_row_major);
    __syncthreads();

    // prologue: stage 0
    load_stage(As[0], Bs[0], 0, row0, col0, nNodes, X, Wp, Ws, tid);
    CP_COMMIT();

    for (int ks = 0; ks < NKS; ks++) {
        const int cur = ks & 1;
        if (ks + 1 < NKS) {
            load_stage(As[cur ^ 1], Bs[cur ^ 1], ks + 1, row0, col0, nNodes,
                       X, Wp, Ws, tid);
            CP_COMMIT();
            CP_WAIT(1);
        } else {
            CP_WAIT(0);
        }
        __syncthreads();

#pragma unroll
        for (int kk8 = 0; kk8 < 2; kk8++) {
            wmma::fragment<wmma::matrix_a, 16, 16, 8, wmma::precision::tf32,
                           wmma::row_major> af[2];
            wmma::fragment<wmma::matrix_b, 16, 16, 8, wmma::precision::tf32,
                           wmma::row_major> bf[4];
#pragma unroll
            for (int mi = 0; mi < 2; mi++) {
                wmma::load_matrix_sync(af[mi], &As[cur][wm * 32 + mi * 16][kk8 * 8], 24);
#pragma unroll
                for (int t = 0; t < af[mi].num_elements; t++)
                    af[mi].x[t] = wmma::__float_to_tf32(af[mi].x[t]);
            }
#pragma unroll
            for (int ni = 0; ni < 4; ni++) {
                wmma::load_matrix_sync(bf[ni], &Bs[cur][kk8 * 8][wn * 64 + ni * 16], 136);
#pragma unroll
                for (int t = 0; t < bf[ni].num_elements; t++)
                    bf[ni].x[t] = wmma::__float_to_tf32(bf[ni].x[t]);
            }
#pragma unroll
            for (int mi = 0; mi < 2; mi++)
#pragma unroll
                for (int ni = 0; ni < 4; ni++)
                    wmma::mma_sync(acc[mi][ni], af[mi], bf[ni], acc[mi][ni]);
        }
        __syncthreads();
    }

    // ReLU on accumulator registers
#pragma unroll
    for (int mi = 0; mi < 2; mi++)
#pragma unroll
        for (int ni = 0; ni < 4; ni++)
#pragma unroll
            for (int t = 0; t < acc[mi][ni].num_elements; t++)
                acc[mi][ni].x[t] = fmaxf(acc[mi][ni].x[t], 0.f);

    if (row0 + 128 <= nNodes) {
#pragma unroll
        for (int mi = 0; mi < 2; mi++)
#pragma unroll
            for (int ni = 0; ni < 4; ni++)
                wmma::store_matrix_sync(
                    out + (size_t)(row0 + wm * 32 + mi * 16) * COUT
                        + col0 + wn * 64 + ni * 16,
                    acc[mi][ni], COUT, wmma::mem_row_major);
    } else {
        // tail CTA: stage 32-row chunks through smem with row guards
        float* stg = &As[0][0][0];   // 32 x 128 staging, row stride 128
        for (int chunk = 0; chunk < 4; chunk++) {
            __syncthreads();
            if (wm == chunk) {
#pragma unroll
                for (int mi = 0; mi < 2; mi++)
#pragma unroll
                    for (int ni = 0; ni < 4; ni++)
                        wmma::store_matrix_sync(
                            stg + (mi * 16) * 128 + wn * 64 + ni * 16,
                            acc[mi][ni], 128, wmma::mem_row_major);
            }
            __syncthreads();
            int base = row0 + chunk * 32;
            for (int idx = tid; idx < 32 * 128; idx += 256) {
                int r = idx >> 7, c = idx & 127;
                int gr = base + r;
                if (gr < nNodes)
                    out[(size_t)gr * COUT + col0 + c] = stg[r * 128 + c];
            }
        }
    }
}

// ---------------------------------------------------------------------------
extern "C" void kernel_launch(void* const* d_in, const int* in_sizes, int n_in,
                              void* d_out, int out_size) {
    const float*  D   = (const float*)d_in[0];
    const int*    row = (const int*)d_in[1];
    const float4* ea  = (const float4*)d_in[2];
    const float*  X   = (const float*)d_in[3];
    const float*  Wp  = (const float*)d_in[4];
    const float*  bp  = (const float*)d_in[5];
    const float*  Ws  = (const float*)d_in[6];
    const float*  bs  = (const float*)d_in[7];
    float* out = (float*)d_out;

    const int nNodes = in_sizes[0];
    const int E      = in_sizes[1];

    // 1) zero accumulator + invD
    {
        int n4 = NODES * CE / 4;
        zero_kernel<<<(n4 + 255) / 256, 256>>>(D);
    }
    // 2) scatter edges (pre-scaled by invD)
    {
        int total16 = E * 16;
        scatter_kernel<<<(total16 + 255) / 256, 256>>>(ea, row, total16);
    }
    // 3) fused GEMM + bias + ReLU
    {
        dim3 grid((nNodes + 127) / 128, COUT / 128);
        gemm_kernel<<<grid, 256>>>(X, Wp, bp, Ws, bs, out, nNodes);
    }
}